// round 11
// baseline (speedup 1.0000x reference)
#include <cuda_runtime.h>
#include <math.h>
#include <float.h>

// Problem constants: B=8, Z=4, X=32, Y=32, N=4096
#define NPTS   4096
#define NB     8
#define THREADS 512
#define NWARP  (THREADS / 32)
#define NITER  (NPTS / THREADS)   // 8
#define MAXK   16
#define CUT2   4.0f               // sqrt(ss) < 2  <=>  ss < 4 (exact)

// Dynamic smem: 8 scalar arrays of NPTS floats
#define SMEM_BYTES (8 * NPTS * 4)

__device__ __forceinline__ float row_angle(float ax, float ay, float az,
                                           float bx, float by, float bz) {
    float na = sqrtf(ax * ax + ay * ay + az * az);
    float nb = sqrtf(bx * bx + by * by + bz * bz);
    float c = (ax * bx + ay * by + az * bz) / (na * nb);
    c = fminf(1.0f, fmaxf(-1.0f, c));
    return (acosf(c) / 3.14159265358979323846f) * 180.0f;
}

__global__ __launch_bounds__(THREADS, 1)
void mol_kernel(const float* __restrict__ pred,
                const float* __restrict__ targ,
                float* __restrict__ out) {
    extern __shared__ float sm[];
    float* s_conf = sm;                 // [NPTS] pred conf (-FLT_MAX = dead)
    float* s_p0 = s_conf + NPTS;        // [NPTS] pred pos normalized
    float* s_p1 = s_p0 + NPTS;
    float* s_p2 = s_p1 + NPTS;
    float* s_tc = s_p2 + NPTS;          // [NPTS] target conf
    float* s_t0 = s_tc + NPTS;          // [NPTS] target pos REAL coords
    float* s_t1 = s_t0 + NPTS;
    float* s_t2 = s_t1 + NPTS;

    __shared__ float wv[NWARP];
    __shared__ int   wiA[NWARP];
    __shared__ int   mW[MAXK][NWARP];   // per-warp matching minima
    __shared__ int   sK, sSel, sNTG;
    __shared__ float selp[3];
    __shared__ int   kId[MAXK];
    __shared__ float kRX[MAXK], kRY[MAXK], kRZ[MAXK];
    __shared__ int   sMatch[MAXK], sHit[MAXK];
    __shared__ float sAngA[MAXK];

    const int tid = threadIdx.x;
    const int lane = tid & 31;
    const int warp = tid >> 5;
    const int b = blockIdx.x;
    const float* P = pred + (long long)b * NPTS * 10;
    const float* T = targ + (long long)b * NPTS * 10;

    // ---- Phase 1: vectorized, fully-unrolled load (R8 verbatim) + count fold ----
    int cnt = 0;
    #pragma unroll
    for (int j = 0; j < NITER; j++) {
        int n = tid + j * THREADS;
        const float* p = P + n * 10;
        const float* t = T + n * 10;
        // 40-byte pitch is 8-byte aligned for every n -> float2 loads legal
        float2 p01 = *(const float2*)p;
        float2 p23 = *(const float2*)(p + 2);
        float2 t01 = *(const float2*)t;
        float2 t23 = *(const float2*)(t + 2);
        float z = (float)(n >> 10), x = (float)((n >> 5) & 31), y = (float)(n & 31);
        // sigmoid(c) > 0.5 <=> c > 0 (exact); /4, /32 exact pow2 mults
        s_conf[n] = (p01.x > 0.0f) ? p01.x : -FLT_MAX;
        s_p0[n] = (p01.y + z) * 0.25f;
        s_p1[n] = (p23.x + x) * 0.03125f;
        s_p2[n] = (p23.y + y) * 0.03125f;
        s_tc[n] = t01.x;
        cnt += (t01.x > 0.5f) ? 1 : 0;
        s_t0[n] = ((t01.y + z) * 0.25f) * 25.0f;   // real coords (×25,25,4)
        s_t1[n] = ((t23.x + x) * 0.03125f) * 25.0f;
        s_t2[n] = ((t23.y + y) * 0.03125f) * 4.0f;
    }
    #pragma unroll
    for (int o = 16; o; o >>= 1) cnt += __shfl_down_sync(0xffffffffu, cnt, o);
    if (lane == 0) wiA[warp] = cnt;
    if (tid == 0) {
        sK = 0;
        selp[0] = 1e30f; selp[1] = 1e30f; selp[2] = 1e30f;  // round 0: kills nothing
    }
    // init matching scratch (read unconditionally later)
    if (tid < MAXK * NWARP) ((int*)mW)[tid] = 0x7fffffff;
    __syncthreads();
    if (tid == 0) {
        int s = 0;
        for (int w = 0; w < NWARP; w++) s += wiA[w];
        sNTG = s;
    }
    __syncthreads();

    // ---- Phase 2: greedy NMS; previous pick's suppression fused into argmax ----
    // (scalar conf scan; pos loaded only for still-alive points)
    for (;;) {
        float c0 = selp[0], c1 = selp[1], c2 = selp[2];
        float bv = -FLT_MAX;
        int bi = 0x7fffffff;
        #pragma unroll
        for (int j = 0; j < NITER; j++) {
            int n = tid + j * THREADS;
            float v = s_conf[n];
            if (v != -FLT_MAX) {
                float d0 = s_p0[n] - c0, d1 = s_p1[n] - c1, d2 = s_p2[n] - c2;
                float ss = (d0 * d0 + d1 * d1) + d2 * d2;
                if (ss < CUT2) { s_conf[n] = -FLT_MAX; v = -FLT_MAX; }
            }
            if (v > bv) { bv = v; bi = n; }   // ascending n keeps lowest idx on tie
        }
        #pragma unroll
        for (int o = 16; o; o >>= 1) {
            float v2 = __shfl_down_sync(0xffffffffu, bv, o);
            int i2 = __shfl_down_sync(0xffffffffu, bi, o);
            if (v2 > bv || (v2 == bv && i2 < bi)) { bv = v2; bi = i2; }
        }
        if (lane == 0) { wv[warp] = bv; wiA[warp] = bi; }
        __syncthreads();
        if (warp == 0) {
            float v = (lane < NWARP) ? wv[lane] : -FLT_MAX;
            int i = (lane < NWARP) ? wiA[lane] : 0x7fffffff;
            #pragma unroll
            for (int o = 8; o; o >>= 1) {
                float v2 = __shfl_down_sync(0xffffffffu, v, o);
                int i2 = __shfl_down_sync(0xffffffffu, i, o);
                if (v2 > v || (v2 == v && i2 < i)) { v = v2; i = i2; }
            }
            if (lane == 0) {
                if (v == -FLT_MAX || sK >= MAXK) {
                    sSel = -1;
                } else {
                    int K = sK;
                    float qx = s_p0[i], qy = s_p1[i], qz = s_p2[i];
                    kId[K] = i;
                    kRX[K] = qx * 25.0f; kRY[K] = qy * 25.0f; kRZ[K] = qz * 4.0f;
                    selp[0] = qx; selp[1] = qy; selp[2] = qz;
                    sK = K + 1;
                    sSel = i;
                }
            }
        }
        __syncthreads();
        if (sSel < 0) break;
    }

    // ---- Phase 3: single-pass matching, best[16] in registers ----
    const int K = sK;
    int best[MAXK];
    #pragma unroll
    for (int kk = 0; kk < MAXK; kk++) best[kk] = 0x7fffffff;
    #pragma unroll
    for (int j = 0; j < NITER; j++) {
        int n = tid + j * THREADS;
        if (s_tc[n] > 0.5f) {
            float a0 = s_t0[n], a1 = s_t1[n], a2 = s_t2[n];
            #pragma unroll
            for (int kk = 0; kk < MAXK; kk++) {
                if (kk < K) {
                    float d0 = a0 - kRX[kk], d1 = a1 - kRY[kk], d2 = a2 - kRZ[kk];
                    float ss = (d0 * d0 + d1 * d1) + d2 * d2;
                    if (ss < CUT2 && n < best[kk]) best[kk] = n;
                }
            }
        }
    }
    #pragma unroll
    for (int kk = 0; kk < MAXK; kk++) {
        if (kk < K) {
            int v = best[kk];
            #pragma unroll
            for (int o = 16; o; o >>= 1) {
                int v2 = __shfl_down_sync(0xffffffffu, v, o);
                if (v2 < v) v = v2;
            }
            if (lane == 0) mW[kk][warp] = v;
        }
    }
    __syncthreads();
    if (warp < K) {                      // ALL 32 lanes participate in shfl
        int v = (lane < NWARP) ? mW[warp][lane] : 0x7fffffff;
        #pragma unroll
        for (int o = 8; o; o >>= 1) {
            int v2 = __shfl_down_sync(0xffffffffu, v, o);
            if (v2 < v) v = v2;
        }
        if (lane == 0) sMatch[warp] = v;
    }
    __syncthreads();

    // ---- Phase 4: K parallel angle computations (global reads, L2-hot) ----
    if (tid < K) {
        int mt = sMatch[tid];
        if (mt != 0x7fffffff) {
            const float* p = P + (long long)kId[tid] * 10 + 4;
            const float* t = T + (long long)mt * 10 + 4;
            float2 pa2 = *(const float2*)p;        // offsets 4..9 are 8B aligned
            float2 pb2 = *(const float2*)(p + 2);
            float2 pc2 = *(const float2*)(p + 4);
            float2 ta2 = *(const float2*)t;
            float2 tb2 = *(const float2*)(t + 2);
            float2 tc2 = *(const float2*)(t + 4);
            float ax = pa2.x, ay = pa2.y, az = pb2.x;
            float bx = pb2.y, by = pc2.x, bz = pc2.y;
            float cx = ay * bz - az * by;
            float cy = az * bx - ax * bz;
            float cz = ax * by - ay * bx;
            float tax = ta2.x, tay = ta2.y, taz = tb2.x;
            float tbx = tb2.y, tby = tc2.x, tbz = tc2.y;
            float tcx = tay * tbz - taz * tby;
            float tcy = taz * tbx - tax * tbz;
            float tcz = tax * tby - tay * tbx;
            sAngA[tid] = row_angle(ax, ay, az, tax, tay, taz)
                       + row_angle(bx, by, bz, tbx, tby, tbz)
                       + row_angle(cx, cy, cz, tcx, tcy, tcz);
            sHit[tid] = 1;
        } else {
            sAngA[tid] = 0.0f;
            sHit[tid] = 0;
        }
    }
    __syncthreads();

    // ---- Phase 5: deterministic epilogue ----
    if (tid == 0) {
        int tp = 0;
        float ang = 0.0f;
        for (int k = 0; k < K; k++) { tp += sHit[k]; ang += sAngA[k]; }
        float tpf = (float)tp;
        out[b * 3 + 0] = tpf;
        out[b * 3 + 1] = (float)K - tpf;
        out[b * 3 + 2] = (float)sNTG - tpf;
        out[3 * NB + b] = (tp > 0) ? (ang / (3.0f * tpf)) : 0.0f;
    }
}

extern "C" void kernel_launch(void* const* d_in, const int* in_sizes, int n_in,
                              void* d_out, int out_size) {
    const float* pred = (const float*)d_in[0];
    const float* targ = (const float*)d_in[1];
    float* out = (float*)d_out;
    cudaFuncSetAttribute(mol_kernel, cudaFuncAttributeMaxDynamicSharedMemorySize,
                         SMEM_BYTES);
    mol_kernel<<<NB, THREADS, SMEM_BYTES>>>(pred, targ, out);
}

// round 12
// speedup vs baseline: 1.1775x; 1.1775x over previous
#include <cuda_runtime.h>
#include <math.h>
#include <float.h>

// Problem constants: B=8, Z=4, X=32, Y=32, N=4096
#define NPTS   4096
#define NB     8
#define THREADS 512
#define NWARP  (THREADS / 32)
#define NITER  (NPTS / THREADS)   // 8
#define MAXK   16
#define REGN   8                  // warp fast path: 32*8 = 256 survivors
#define CUT2   4.0f               // sqrt(ss) < 2  <=>  ss < 4 (exact)

// smem: 7 point arrays (conf,p0,p1,p2,t0,t1,t2) + survivor SoA (5 * NPTS)
#define SMEM_BYTES ((7 * NPTS + 5 * NPTS) * 4)

__device__ __forceinline__ float row_angle(float ax, float ay, float az,
                                           float bx, float by, float bz) {
    float na = sqrtf(ax * ax + ay * ay + az * az);
    float nb = sqrtf(bx * bx + by * by + bz * bz);
    float c = (ax * bx + ay * by + az * bz) / (na * nb);
    c = fminf(1.0f, fmaxf(-1.0f, c));
    return (acosf(c) / 3.14159265358979323846f) * 180.0f;
}

__global__ __launch_bounds__(THREADS, 1)
void mol_kernel(const float* __restrict__ pred,
                const float* __restrict__ targ,
                float* __restrict__ out) {
    extern __shared__ float sm[];
    float* s_conf = sm;                 // [NPTS] pred conf (-FLT_MAX = inactive)
    float* s_p0 = s_conf + NPTS;        // [NPTS] pred pos normalized
    float* s_p1 = s_p0 + NPTS;
    float* s_p2 = s_p1 + NPTS;
    float* s_t0 = s_p2 + NPTS;          // [NPTS] targ real coords (t0: 1e30 = inactive)
    float* s_t1 = s_t0 + NPTS;
    float* s_t2 = s_t1 + NPTS;
    float* svC = s_t2 + NPTS;           // [NPTS] survivor SoA
    float* svX = svC + NPTS;
    float* svY = svX + NPTS;
    float* svZ = svY + NPTS;
    int*   svI = (int*)(svZ + NPTS);

    __shared__ unsigned long long sMax;
    __shared__ int   wCnt[NWARP];
    __shared__ float wv[NWARP];
    __shared__ int   wiA[NWARP];
    __shared__ int   sS, sK, sCont;
    __shared__ float sSelX, sSelY, sSelZ;
    __shared__ int   kId[MAXK];
    __shared__ float kRX[MAXK], kRY[MAXK], kRZ[MAXK];
    __shared__ int   sMatch[MAXK], sHit[MAXK];
    __shared__ float sAngA[MAXK];

    const int tid = threadIdx.x;
    const int lane = tid & 31;
    const int warp = tid >> 5;
    const unsigned lt = (1u << lane) - 1u;
    const int b = blockIdx.x;
    const float* P = pred + (long long)b * NPTS * 10;
    const float* T = targ + (long long)b * NPTS * 10;

    if (tid == 0) { sMax = 0ull; sS = 0; sK = 0; }
    if (tid < MAXK) sMatch[tid] = 0x7fffffff;
    __syncthreads();

    // ---- Phase 1: R8 load verbatim + fold target count + fold round-0 argmax ----
    int cnt = 0;
    unsigned long long pk = 0ull;
    #pragma unroll
    for (int j = 0; j < NITER; j++) {
        int n = tid + j * THREADS;
        const float* p = P + n * 10;
        const float* t = T + n * 10;
        // 40-byte pitch is 8-byte aligned for every n -> float2 loads legal
        float2 p01 = *(const float2*)p;
        float2 p23 = *(const float2*)(p + 2);
        float2 t01 = *(const float2*)t;
        float2 t23 = *(const float2*)(t + 2);
        float z = (float)(n >> 10), x = (float)((n >> 5) & 31), y = (float)(n & 31);
        float pc = p01.x;
        // sigmoid(c) > 0.5 <=> c > 0 (exact); /4, /32 exact pow2 mults
        s_conf[n] = (pc > 0.0f) ? pc : -FLT_MAX;
        s_p0[n] = (p01.y + z) * 0.25f;
        s_p1[n] = (p23.x + x) * 0.03125f;
        s_p2[n] = (p23.y + y) * 0.03125f;
        bool act = t01.x > 0.5f;
        cnt += act ? 1 : 0;
        // real coords; inactive -> sentinel kills every distance test
        s_t0[n] = act ? ((t01.y + z) * 0.25f) * 25.0f : 1e30f;
        s_t1[n] = ((t23.x + x) * 0.03125f) * 25.0f;
        s_t2[n] = ((t23.y + y) * 0.03125f) * 4.0f;
        // packed argmax: conf>0 has order-preserving uint bits; tie -> lower n
        if (pc > 0.0f) {
            unsigned long long q = (((unsigned long long)__float_as_uint(pc)) << 32)
                                 | (unsigned long long)(NPTS - n);
            if (q > pk) pk = q;
        }
    }
    #pragma unroll
    for (int o = 16; o; o >>= 1) {
        unsigned long long q = __shfl_down_sync(0xffffffffu, pk, o);
        if (q > pk) pk = q;
        cnt += __shfl_down_sync(0xffffffffu, cnt, o);
    }
    if (lane == 0) {
        wCnt[warp] = cnt;
        if (pk) atomicMax(&sMax, pk);
    }
    __syncthreads();

    // ---- Phase 2: pick 0 (all threads unpack), suppress + compact survivors ----
    unsigned long long mx = sMax;
    if (mx != 0ull) {
        int i0 = NPTS - (int)(mx & 0xffffffffu);
        float c0 = s_p0[i0], c1 = s_p1[i0], c2 = s_p2[i0];   // LDS broadcast
        if (tid == 0) {
            kId[0] = i0;
            kRX[0] = c0 * 25.0f; kRY[0] = c1 * 25.0f; kRZ[0] = c2 * 4.0f;
            sK = 1;
        }
        #pragma unroll
        for (int j = 0; j < NITER; j++) {
            int n = tid + j * THREADS;
            float v = s_conf[n];
            bool f = false;
            float px = 0, py = 0, pz = 0;
            if (v != -FLT_MAX) {
                px = s_p0[n]; py = s_p1[n]; pz = s_p2[n];
                float d0 = px - c0, d1 = py - c1, d2 = pz - c2;
                float ss = (d0 * d0 + d1 * d1) + d2 * d2;
                f = (ss >= CUT2);               // survivor of pick0's ball
            }
            unsigned m = __ballot_sync(0xffffffffu, f);
            int base = 0;
            if (lane == 0 && m) base = atomicAdd(&sS, __popc(m));
            base = __shfl_sync(0xffffffffu, base, 0);
            if (f) {
                int s = base + __popc(m & lt);
                svC[s] = v; svX[s] = px; svY[s] = py; svZ[s] = pz; svI[s] = n;
            }
        }
    }
    __syncthreads();
    const int S = sS;

    // ---- Phase 3: remaining greedy rounds ----
    if (mx != 0ull && S > 0) {
        if (S <= 32 * REGN) {
            // fast path: warp 0 finishes all rounds in registers, no block barriers
            if (warp == 0) {
                float c8[REGN], x8[REGN], y8[REGN], z8[REGN];
                int i8[REGN];
                #pragma unroll
                for (int j = 0; j < REGN; j++) {
                    int e = lane + j * 32;
                    c8[j] = -FLT_MAX; i8[j] = 0x7fffffff;
                    x8[j] = 0.0f; y8[j] = 0.0f; z8[j] = 0.0f;
                    if (e < S) {
                        c8[j] = svC[e]; x8[j] = svX[e]; y8[j] = svY[e]; z8[j] = svZ[e];
                        i8[j] = svI[e];
                    }
                }
                int K = 1;
                while (K < MAXK) {
                    float bv = -FLT_MAX, bx = 0.0f, by = 0.0f, bz = 0.0f;
                    int bk = 0x7fffffff;
                    #pragma unroll
                    for (int j = 0; j < REGN; j++) {
                        if (c8[j] > bv || (c8[j] == bv && i8[j] < bk)) {
                            bv = c8[j]; bk = i8[j]; bx = x8[j]; by = y8[j]; bz = z8[j];
                        }
                    }
                    #pragma unroll
                    for (int o = 16; o; o >>= 1) {
                        float v2 = __shfl_xor_sync(0xffffffffu, bv, o);
                        int k2 = __shfl_xor_sync(0xffffffffu, bk, o);
                        float x2 = __shfl_xor_sync(0xffffffffu, bx, o);
                        float y2 = __shfl_xor_sync(0xffffffffu, by, o);
                        float z2 = __shfl_xor_sync(0xffffffffu, bz, o);
                        if (v2 > bv || (v2 == bv && k2 < bk)) {
                            bv = v2; bk = k2; bx = x2; by = y2; bz = z2;
                        }
                    }
                    if (bv == -FLT_MAX) break;
                    if (lane == 0) {
                        kId[K] = bk;
                        kRX[K] = bx * 25.0f; kRY[K] = by * 25.0f; kRZ[K] = bz * 4.0f;
                    }
                    K++;
                    #pragma unroll
                    for (int j = 0; j < REGN; j++) {
                        float d0 = x8[j] - bx, d1 = y8[j] - by, d2 = z8[j] - bz;
                        float ss = (d0 * d0 + d1 * d1) + d2 * d2;
                        if (ss < CUT2) c8[j] = -FLT_MAX;
                    }
                }
                if (lane == 0) sK = K;
            }
        } else {
            // fallback: block-wide rounds over survivor arrays (uniform branch)
            for (;;) {
                float bv = -FLT_MAX;
                int bk = 0x7fffffff, bs = -1;
                for (int e = tid; e < S; e += THREADS) {
                    float v = svC[e];
                    if (v != -FLT_MAX) {
                        int id = svI[e];
                        if (v > bv || (v == bv && id < bk)) { bv = v; bk = id; bs = e; }
                    }
                }
                #pragma unroll
                for (int o = 16; o; o >>= 1) {
                    float v2 = __shfl_down_sync(0xffffffffu, bv, o);
                    int k2 = __shfl_down_sync(0xffffffffu, bk, o);
                    int s2 = __shfl_down_sync(0xffffffffu, bs, o);
                    if (v2 > bv || (v2 == bv && k2 < bk)) { bv = v2; bk = k2; bs = s2; }
                }
                if (lane == 0) { wv[warp] = bv; wiA[warp] = bs >= 0 ? bs : 0x7fffffff; }
                __syncthreads();
                if (warp == 0) {
                    float v = (lane < NWARP) ? wv[lane] : -FLT_MAX;
                    int s = (lane < NWARP) ? wiA[lane] : 0x7fffffff;
                    int k = (s != 0x7fffffff) ? svI[s] : 0x7fffffff;
                    #pragma unroll
                    for (int o = 8; o; o >>= 1) {
                        float v2 = __shfl_down_sync(0xffffffffu, v, o);
                        int k2 = __shfl_down_sync(0xffffffffu, k, o);
                        int s2 = __shfl_down_sync(0xffffffffu, s, o);
                        if (v2 > v || (v2 == v && k2 < k)) { v = v2; k = k2; s = s2; }
                    }
                    if (lane == 0) {
                        if (v == -FLT_MAX || sK >= MAXK) {
                            sCont = 0;
                        } else {
                            int K = sK;
                            kId[K] = k;
                            kRX[K] = svX[s] * 25.0f; kRY[K] = svY[s] * 25.0f;
                            kRZ[K] = svZ[s] * 4.0f;
                            sSelX = svX[s]; sSelY = svY[s]; sSelZ = svZ[s];
                            sK = K + 1;
                            sCont = 1;
                        }
                    }
                }
                __syncthreads();
                if (!sCont) break;
                float cx = sSelX, cy = sSelY, cz = sSelZ;
                for (int e = tid; e < S; e += THREADS) {
                    if (svC[e] != -FLT_MAX) {
                        float d0 = svX[e] - cx, d1 = svY[e] - cy, d2 = svZ[e] - cz;
                        float ss = (d0 * d0 + d1 * d1) + d2 * d2;
                        if (ss < CUT2) svC[e] = -FLT_MAX;
                    }
                }
                __syncthreads();
            }
        }
    }
    __syncthreads();

    // ---- Phase 4: single matching scan, dynamic k loop, atomicMin on hits ----
    const int K = sK;
    #pragma unroll
    for (int j = 0; j < NITER; j++) {
        int n = tid + j * THREADS;
        float a0 = s_t0[n];
        if (a0 < 1e29f) {                   // active target
            float a1 = s_t1[n], a2 = s_t2[n];
            for (int k = 0; k < K; k++) {
                float d0 = a0 - kRX[k], d1 = a1 - kRY[k], d2 = a2 - kRZ[k];
                float ss = (d0 * d0 + d1 * d1) + d2 * d2;
                if (ss < CUT2) atomicMin(&sMatch[k], n);   // rare; commutative
            }
        }
    }
    __syncthreads();

    // ---- Phase 5: K parallel angle computations ----
    if (tid < K) {
        int mt = sMatch[tid];
        if (mt != 0x7fffffff) {
            const float* p = P + (long long)kId[tid] * 10 + 4;
            const float* t = T + (long long)mt * 10 + 4;
            float2 pa2 = *(const float2*)p;        // offsets 4..9 are 8B aligned
            float2 pb2 = *(const float2*)(p + 2);
            float2 pc2 = *(const float2*)(p + 4);
            float2 ta2 = *(const float2*)t;
            float2 tb2 = *(const float2*)(t + 2);
            float2 tc2 = *(const float2*)(t + 4);
            float ax = pa2.x, ay = pa2.y, az = pb2.x;
            float bx = pb2.y, by = pc2.x, bz = pc2.y;
            float cx = ay * bz - az * by;
            float cy = az * bx - ax * bz;
            float cz = ax * by - ay * bx;
            float tax = ta2.x, tay = ta2.y, taz = tb2.x;
            float tbx = tb2.y, tby = tc2.x, tbz = tc2.y;
            float tcx = tay * tbz - taz * tby;
            float tcy = taz * tbx - tax * tbz;
            float tcz = tax * tby - tay * tbx;
            sAngA[tid] = row_angle(ax, ay, az, tax, tay, taz)
                       + row_angle(bx, by, bz, tbx, tby, tbz)
                       + row_angle(cx, cy, cz, tcx, tcy, tcz);
            sHit[tid] = 1;
        } else {
            sAngA[tid] = 0.0f;
            sHit[tid] = 0;
        }
    }
    __syncthreads();

    // ---- Phase 6: deterministic epilogue ----
    if (tid == 0) {
        int ntg = 0;
        for (int w = 0; w < NWARP; w++) ntg += wCnt[w];
        int tp = 0;
        float ang = 0.0f;
        for (int k = 0; k < K; k++) { tp += sHit[k]; ang += sAngA[k]; }
        float tpf = (float)tp;
        out[b * 3 + 0] = tpf;
        out[b * 3 + 1] = (float)K - tpf;
        out[b * 3 + 2] = (float)ntg - tpf;
        out[3 * NB + b] = (tp > 0) ? (ang / (3.0f * tpf)) : 0.0f;
    }
}

extern "C" void kernel_launch(void* const* d_in, const int* in_sizes, int n_in,
                              void* d_out, int out_size) {
    const float* pred = (const float*)d_in[0];
    const float* targ = (const float*)d_in[1];
    float* out = (float*)d_out;
    cudaFuncSetAttribute(mol_kernel, cudaFuncAttributeMaxDynamicSharedMemorySize,
                         SMEM_BYTES);
    mol_kernel<<<NB, THREADS, SMEM_BYTES>>>(pred, targ, out);
}

// round 13
// speedup vs baseline: 1.1805x; 1.0025x over previous
#include <cuda_runtime.h>
#include <math.h>
#include <float.h>

// Problem constants (from reference): B=8, Z=4, X=32, Y=32, N=4096
#define NPTS   4096
#define NB     8
#define THREADS 512
#define NWARP  (THREADS / 32)
#define NITER  (NPTS / THREADS)   // 8
#define MAXKEEP 32
#define CUT2   4.0f               // sqrt(ss) < 2  <=>  ss < 4 (exact)

// Dynamic smem: 8 arrays of NPTS floats + warp scratch + kept arrays
#define SMEM_BYTES ((8 * NPTS + 2 * NWARP + 4 * MAXKEEP) * 4)

__device__ __forceinline__ float row_angle(float ax, float ay, float az,
                                           float bx, float by, float bz) {
    float na = sqrtf(ax * ax + ay * ay + az * az);
    float nb = sqrtf(bx * bx + by * by + bz * bz);
    float c = (ax * bx + ay * by + az * bz) / (na * nb);
    c = fminf(1.0f, fmaxf(-1.0f, c));
    return (acosf(c) / 3.14159265358979323846f) * 180.0f;
}

__global__ __launch_bounds__(THREADS, 1)
void mol_kernel(const float* __restrict__ pred,
                const float* __restrict__ targ,
                float* __restrict__ out) {
    extern __shared__ float sm[];
    float* s_conf = sm;                 // [NPTS] pred conf (raw, -FLT_MAX = inactive)
    float* s_p0 = s_conf + NPTS;        // [NPTS] pred pos normalized
    float* s_p1 = s_p0 + NPTS;
    float* s_p2 = s_p1 + NPTS;
    float* s_t0 = s_p2 + NPTS;          // [NPTS] target pos in REAL coords
    float* s_t1 = s_t0 + NPTS;
    float* s_t2 = s_t1 + NPTS;
    float* s_tc = s_t2 + NPTS;          // [NPTS] target conf
    float* wv = s_tc + NPTS;            // [NWARP]
    int* wi = (int*)(wv + NWARP);       // [NWARP]
    float* kx = (float*)(wi + NWARP);   // kept point normalized coords
    float* ky = kx + MAXKEEP;
    float* kz = ky + MAXKEEP;
    int* kid = (int*)(kz + MAXKEEP);    // kept original indices

    __shared__ int sK, sSel, sNTG;
    __shared__ float selp[3];
    __shared__ int   sMatch[MAXKEEP], sHit[MAXKEEP];
    __shared__ float sAngA[MAXKEEP];

    const int tid = threadIdx.x;
    const int lane = tid & 31;
    const int warp = tid >> 5;
    const int b = blockIdx.x;
    const float* P = pred + (long long)b * NPTS * 10;
    const float* T = targ + (long long)b * NPTS * 10;

    // ---- Phase 1: vectorized, fully-unrolled load (R8 verbatim) + count fold ----
    int cnt = 0;
    #pragma unroll
    for (int j = 0; j < NITER; j++) {
        int n = tid + j * THREADS;
        const float* p = P + n * 10;
        const float* t = T + n * 10;
        // 40-byte pitch is 8-byte aligned for every n -> float2 loads legal
        float2 p01 = *(const float2*)p;
        float2 p23 = *(const float2*)(p + 2);
        float2 t01 = *(const float2*)t;
        float2 t23 = *(const float2*)(t + 2);
        float z = (float)(n >> 10), x = (float)((n >> 5) & 31), y = (float)(n & 31);
        // sigmoid(c) > 0.5  <=>  c > 0  (exact)
        s_conf[n] = (p01.x > 0.0f) ? p01.x : -FLT_MAX;
        // normalized pos: (offset + cell)/ZXY ; /4 and /32 are exact pow2 mults
        s_p0[n] = (p01.y + z) * 0.25f;
        s_p1[n] = (p23.x + x) * 0.03125f;
        s_p2[n] = (p23.y + y) * 0.03125f;
        // target: real coords = normalized * REAL_SIZE(25,25,4)
        s_tc[n] = t01.x;
        cnt += (t01.x > 0.5f) ? 1 : 0;
        s_t0[n] = ((t01.y + z) * 0.25f) * 25.0f;
        s_t1[n] = ((t23.x + x) * 0.03125f) * 25.0f;
        s_t2[n] = ((t23.y + y) * 0.03125f) * 4.0f;
    }
    #pragma unroll
    for (int o = 16; o; o >>= 1) cnt += __shfl_down_sync(0xffffffffu, cnt, o);
    if (lane == 0) wi[warp] = cnt;
    if (tid == 0) sK = 0;
    if (tid < MAXKEEP) sMatch[tid] = 0x7fffffff;
    __syncthreads();
    if (tid == 0) {          // consume wi before rounds reuse it
        int s = 0;
        for (int w = 0; w < NWARP; w++) s += wi[w];
        sNTG = s;
    }
    __syncthreads();

    // ---- Phase 2: round-based greedy NMS (R8 structure, untouched) ----
    for (;;) {
        // block argmax over remaining confidence (tie -> lowest index)
        float bv = -FLT_MAX;
        int bi = 0x7fffffff;
        #pragma unroll
        for (int j = 0; j < NITER; j++) {
            int n = tid + j * THREADS;
            float v = s_conf[n];
            if (v > bv) { bv = v; bi = n; }   // ascending n => ties keep lowest idx
        }
        #pragma unroll
        for (int o = 16; o; o >>= 1) {
            float v2 = __shfl_down_sync(0xffffffffu, bv, o);
            int i2 = __shfl_down_sync(0xffffffffu, bi, o);
            if (v2 > bv || (v2 == bv && i2 < bi)) { bv = v2; bi = i2; }
        }
        if (lane == 0) { wv[warp] = bv; wi[warp] = bi; }
        __syncthreads();
        if (warp == 0) {
            float v = (lane < NWARP) ? wv[lane] : -FLT_MAX;
            int i = (lane < NWARP) ? wi[lane] : 0x7fffffff;
            #pragma unroll
            for (int o = 8; o; o >>= 1) {
                float v2 = __shfl_down_sync(0xffffffffu, v, o);
                int i2 = __shfl_down_sync(0xffffffffu, i, o);
                if (v2 > v || (v2 == v && i2 < i)) { v = v2; i = i2; }
            }
            if (lane == 0) {
                if (v == -FLT_MAX || sK >= MAXKEEP) {
                    sSel = -1;
                } else {
                    sSel = i;
                    int K = sK;
                    kx[K] = s_p0[i]; ky[K] = s_p1[i]; kz[K] = s_p2[i]; kid[K] = i;
                    selp[0] = s_p0[i]; selp[1] = s_p1[i]; selp[2] = s_p2[i];
                    sK = K + 1;
                }
            }
        }
        __syncthreads();
        if (sSel < 0) break;
        // suppress everything within CUT of selected (includes itself, d=0)
        float c0 = selp[0], c1 = selp[1], c2 = selp[2];
        #pragma unroll
        for (int j = 0; j < NITER; j++) {
            int n = tid + j * THREADS;
            if (s_conf[n] != -FLT_MAX) {
                float d0 = s_p0[n] - c0, d1 = s_p1[n] - c1, d2 = s_p2[n] - c2;
                float ss = (d0 * d0 + d1 * d1) + d2 * d2;
                if (ss < CUT2) s_conf[n] = -FLT_MAX;
            }
        }
        __syncthreads();
    }

    // ---- Phase 3: single-pass matching (atomicMin on rare hits) ----
    const int K = sK;
    #pragma unroll
    for (int j = 0; j < NITER; j++) {
        int n = tid + j * THREADS;
        if (s_tc[n] > 0.5f) {
            float a0 = s_t0[n], a1 = s_t1[n], a2 = s_t2[n];
            for (int k = 0; k < K; k++) {
                float d0 = a0 - kx[k] * 25.0f;
                float d1 = a1 - ky[k] * 25.0f;
                float d2 = a2 - kz[k] * 4.0f;
                float ss = (d0 * d0 + d1 * d1) + d2 * d2;
                if (ss < CUT2) atomicMin(&sMatch[k], n);  // min n == first match
            }
        }
    }
    __syncthreads();

    // ---- Phase 4: K parallel angle computations (global reads, L2-hot) ----
    if (tid < K) {
        int mt = sMatch[tid];
        if (mt != 0x7fffffff) {
            const float* p = P + (long long)kid[tid] * 10 + 4;
            const float* t = T + (long long)mt * 10 + 4;
            float2 pa2 = *(const float2*)p;        // offsets 4..9 are 8B aligned
            float2 pb2 = *(const float2*)(p + 2);
            float2 pc2 = *(const float2*)(p + 4);
            float2 ta2 = *(const float2*)t;
            float2 tb2 = *(const float2*)(t + 2);
            float2 tc2 = *(const float2*)(t + 4);
            float ax = pa2.x, ay = pa2.y, az = pb2.x;
            float bx = pb2.y, by = pc2.x, bz = pc2.y;
            float cx = ay * bz - az * by;
            float cy = az * bx - ax * bz;
            float cz = ax * by - ay * bx;
            float tax = ta2.x, tay = ta2.y, taz = tb2.x;
            float tbx = tb2.y, tby = tc2.x, tbz = tc2.y;
            float tcx = tay * tbz - taz * tby;
            float tcy = taz * tbx - tax * tbz;
            float tcz = tax * tby - tay * tbx;
            sAngA[tid] = row_angle(ax, ay, az, tax, tay, taz)
                       + row_angle(bx, by, bz, tbx, tby, tbz)
                       + row_angle(cx, cy, cz, tcx, tcy, tcz);
            sHit[tid] = 1;
        } else {
            sAngA[tid] = 0.0f;
            sHit[tid] = 0;
        }
    }
    __syncthreads();

    // ---- Phase 5: deterministic epilogue ----
    if (tid == 0) {
        int tp = 0;
        float ang = 0.0f;
        for (int k = 0; k < K; k++) { tp += sHit[k]; ang += sAngA[k]; }
        float tpf = (float)tp;
        out[b * 3 + 0] = tpf;
        out[b * 3 + 1] = (float)K - tpf;
        out[b * 3 + 2] = (float)sNTG - tpf;
        out[3 * NB + b] = (tp > 0) ? (ang / (3.0f * tpf)) : 0.0f;
    }
}

extern "C" void kernel_launch(void* const* d_in, const int* in_sizes, int n_in,
                              void* d_out, int out_size) {
    const float* pred = (const float*)d_in[0];
    const float* targ = (const float*)d_in[1];
    float* out = (float*)d_out;
    cudaFuncSetAttribute(mol_kernel, cudaFuncAttributeMaxDynamicSharedMemorySize,
                         SMEM_BYTES);
    mol_kernel<<<NB, THREADS, SMEM_BYTES>>>(pred, targ, out);
}